// round 3
// baseline (speedup 1.0000x reference)
#include <cuda_runtime.h>
#include <cuda_bf16.h>
#include <cstdint>

#define T_TOKENS 8192
#define D_DIM    768
#define E_EXPERTS 8
#define CAPACITY 2048

// Scratch (device globals — allocation is forbidden)
__device__ int      g_eidx[T_TOKENS];
__device__ float    g_gate[T_TOKENS];
__device__ int      g_pos[T_TOKENS];
__device__ unsigned g_router_done;
__device__ unsigned g_fill_done;

// ---------------------------------------------------------------------------
__global__ void init_kernel()
{
    g_router_done = 0;
    g_fill_done   = 0;
}

// ---------------------------------------------------------------------------
// Role helpers (all inlined into one fused kernel, blockDim = 256)
// ---------------------------------------------------------------------------
__device__ __forceinline__ void do_router(int r, const float* __restrict__ x,
                                          const float* __restrict__ W,
                                          float* Wt /* smem [E][D] */)
{
    for (int i = threadIdx.x; i < D_DIM * E_EXPERTS; i += 256) {
        int d = i >> 3, e = i & 7;
        Wt[e * D_DIM + d] = W[i];
    }
    __syncthreads();

    const int warp = threadIdx.x >> 5;
    const int lane = threadIdx.x & 31;
    const int t = r * 8 + warp;

    const float4* xr = (const float4*)(x + (size_t)t * D_DIM);
    float acc[E_EXPERTS];
#pragma unroll
    for (int e = 0; e < E_EXPERTS; ++e) acc[e] = 0.f;

#pragma unroll
    for (int i = 0; i < D_DIM / 128; ++i) {          // 6 iterations
        const int f4 = lane + 32 * i;
        float4 xv = xr[f4];
#pragma unroll
        for (int e = 0; e < E_EXPERTS; ++e) {
            float4 wv = *(const float4*)&Wt[e * D_DIM + 4 * f4];
            acc[e] = fmaf(xv.x, wv.x, acc[e]);
            acc[e] = fmaf(xv.y, wv.y, acc[e]);
            acc[e] = fmaf(xv.z, wv.z, acc[e]);
            acc[e] = fmaf(xv.w, wv.w, acc[e]);
        }
    }
#pragma unroll
    for (int off = 16; off > 0; off >>= 1)
#pragma unroll
        for (int e = 0; e < E_EXPERTS; ++e)
            acc[e] += __shfl_xor_sync(0xffffffffu, acc[e], off);

    if (lane == 0) {
        float m = acc[0]; int bi = 0;
#pragma unroll
        for (int e = 1; e < E_EXPERTS; ++e)
            if (acc[e] > m) { m = acc[e]; bi = e; }   // strict > = first-index ties
        float s = 0.f;
#pragma unroll
        for (int e = 0; e < E_EXPERTS; ++e)
            s += __expf(acc[e] - m);
        g_gate[t] = 1.0f / s;
        g_eidx[t] = bi;
    }
    // release: results visible before counter bump
    __threadfence();
    __syncthreads();
    if (threadIdx.x == 0) atomicAdd(&g_router_done, 1u);
}

__device__ __forceinline__ void do_fill(int t, float* __restrict__ out)
{
    // Pure zero fill of token t's 128 KiB (both tensors). No dependencies.
    const size_t TEC4 = (size_t)T_TOKENS * E_EXPERTS * (CAPACITY / 4);
    float4* d0 = (float4*)out + (size_t)t * E_EXPERTS * (CAPACITY / 4);
    float4* d1 = d0 + TEC4;
    const float4 z = make_float4(0.f, 0.f, 0.f, 0.f);
#pragma unroll
    for (int e = 0; e < E_EXPERTS; ++e)
#pragma unroll
        for (int k = 0; k < 2; ++k) {
            const int i = threadIdx.x + k * 256;      // 0..511 float4s
            d0[e * (CAPACITY / 4) + i] = z;
            d1[e * (CAPACITY / 4) + i] = z;
        }
    __threadfence();
    __syncthreads();
    if (threadIdx.x == 0) atomicAdd(&g_fill_done, 1u);
}

__device__ __forceinline__ void do_scan_scatter(float* __restrict__ out,
                                                int* s_cnt /* [8 warps][8] */,
                                                int* s_off /* [8 warps][8] */,
                                                int* s_base /* [8] */)
{
    const int tid  = threadIdx.x;
    const int warp = tid >> 5;
    const int lane = tid & 31;

    // acquire router results
    if (tid == 0) {
        while (*((volatile unsigned*)&g_router_done) < (T_TOKENS / 8)) __nanosleep(64);
        __threadfence();
    }
    __syncthreads();

    if (tid < E_EXPERTS) s_base[tid] = 0;
    __syncthreads();

    for (int r = 0; r < T_TOKENS / 256; ++r) {        // 32 rounds
        const int t = r * 256 + tid;
        const int e = __ldcg(&g_eidx[t]);
        int myrank = 0;
#pragma unroll
        for (int ex = 0; ex < E_EXPERTS; ++ex) {
            unsigned b = __ballot_sync(0xffffffffu, e == ex);
            if (e == ex) myrank = __popc(b & ((1u << lane) - 1u));
            if (lane == 0) s_cnt[warp * 8 + ex] = __popc(b);
        }
        __syncthreads();
        if (tid < E_EXPERTS) {                        // thread per expert: scan 8 warps
            const int ex = tid;
            int run = s_base[ex];
#pragma unroll
            for (int w = 0; w < 8; ++w) {
                s_off[w * 8 + ex] = run;
                run += s_cnt[w * 8 + ex];
            }
            s_base[ex] = run;
        }
        __syncthreads();
        const int pos = s_off[warp * 8 + e] + myrank + 1;   // 1-based
        g_pos[t] = (pos < CAPACITY) ? pos : 0;
        __syncthreads();
    }

    // wait for every zero-fill block, then scatter the 16K nonzeros
    if (tid == 0) {
        while (*((volatile unsigned*)&g_fill_done) < T_TOKENS) __nanosleep(128);
        __threadfence();
    }
    __syncthreads();

    const size_t TEC = (size_t)T_TOKENS * E_EXPERTS * CAPACITY;
    for (int t = tid; t < T_TOKENS; t += 256) {
        const int pos = g_pos[t];
        if (pos == 0) continue;
        const int e = __ldcg(&g_eidx[t]);
        const size_t idx = ((size_t)t * E_EXPERTS + e) * CAPACITY + pos;
        out[idx]       = 1.0f;
        out[TEC + idx] = __ldcg(&g_gate[t]);
    }
}

// ---------------------------------------------------------------------------
// Fused kernel: grid = 9217.
//   bid 0                : scan + scatter (spins; critical path hidden under fill)
//   bid 1..2048, odd     : router block (bid-1)/2          (1024 blocks)
//   bid 1..2048, even    : fill token bid/2 - 1            (1024 tokens)
//   bid 2049..9216       : fill token bid - 1025           (tokens 1024..8191)
// ---------------------------------------------------------------------------
__global__ __launch_bounds__(256) void fused_kernel(const float* __restrict__ x,
                                                    const float* __restrict__ W,
                                                    float* __restrict__ out)
{
    __shared__ float Wt[E_EXPERTS * D_DIM];           // 24 KB (router blocks)
    __shared__ int   s_cnt[8 * E_EXPERTS];
    __shared__ int   s_off[8 * E_EXPERTS];
    __shared__ int   s_base[E_EXPERTS];

    const int bid = blockIdx.x;
    if (bid == 0) {
        do_scan_scatter(out, s_cnt, s_off, s_base);
    } else if (bid <= 2048) {
        if (bid & 1) do_router((bid - 1) >> 1, x, W, Wt);
        else         do_fill(bid / 2 - 1, out);
    } else {
        do_fill(bid - 1025, out);
    }
}

// ---------------------------------------------------------------------------
extern "C" void kernel_launch(void* const* d_in, const int* in_sizes, int n_in,
                              void* d_out, int out_size)
{
    const float* x = (const float*)d_in[0];
    const float* W = (const float*)d_in[1];
    float* out = (float*)d_out;

    init_kernel<<<1, 1>>>();                 // reset counters every replay
    fused_kernel<<<1 + 2048 + (T_TOKENS - 1024), 256>>>(x, W, out);
}

// round 5
// speedup vs baseline: 1.2704x; 1.2704x over previous
#include <cuda_runtime.h>
#include <cuda_bf16.h>
#include <cstdint>

#define T_TOKENS 8192
#define D_DIM    768
#define E_EXPERTS 8
#define CAPACITY 2048

#define N_ROUTER_BLOCKS 256
#define SCAN_BID        N_ROUTER_BLOCKS
#define FILL_BASE       (N_ROUTER_BLOCKS + 1)

// Scratch (device globals — allocation is forbidden)
__device__ int      g_eidx[T_TOKENS];
__device__ float    g_gate[T_TOKENS];
__device__ int      g_pos[T_TOKENS];   // 1..2047 kept, 0 dropped
__device__ unsigned g_router_done;

// ---------------------------------------------------------------------------
__global__ void init_kernel() { g_router_done = 0; }

// ---------------------------------------------------------------------------
// Router: warp handles 4 tokens, W float4 reused across them (LDS traffic /4).
// 256 blocks x 8 warps x 4 tokens = 8192.
// ---------------------------------------------------------------------------
__device__ __forceinline__ void do_router(int bid, const float* __restrict__ x,
                                          const float* __restrict__ W,
                                          float (*Wt)[D_DIM])
{
    for (int i = threadIdx.x; i < D_DIM * E_EXPERTS; i += 256) {
        int d = i >> 3, e = i & 7;
        Wt[e][d] = W[i];
    }
    __syncthreads();

    const int warp = threadIdx.x >> 5;
    const int lane = threadIdx.x & 31;
    const int t0 = (bid * 8 + warp) * 4;

    float acc[4][E_EXPERTS];
#pragma unroll
    for (int tk = 0; tk < 4; ++tk)
#pragma unroll
        for (int e = 0; e < E_EXPERTS; ++e) acc[tk][e] = 0.f;

#pragma unroll
    for (int i = 0; i < D_DIM / 128; ++i) {       // 6 iterations
        const int f4 = lane + 32 * i;
        float4 wv[E_EXPERTS];
#pragma unroll
        for (int e = 0; e < E_EXPERTS; ++e)
            wv[e] = *(const float4*)&Wt[e][4 * f4];
#pragma unroll
        for (int tk = 0; tk < 4; ++tk) {
            float4 xv = ((const float4*)(x + (size_t)(t0 + tk) * D_DIM))[f4];
#pragma unroll
            for (int e = 0; e < E_EXPERTS; ++e) {
                acc[tk][e] = fmaf(xv.x, wv[e].x, acc[tk][e]);
                acc[tk][e] = fmaf(xv.y, wv[e].y, acc[tk][e]);
                acc[tk][e] = fmaf(xv.z, wv[e].z, acc[tk][e]);
                acc[tk][e] = fmaf(xv.w, wv[e].w, acc[tk][e]);
            }
        }
    }
#pragma unroll
    for (int off = 16; off > 0; off >>= 1)
#pragma unroll
        for (int tk = 0; tk < 4; ++tk)
#pragma unroll
            for (int e = 0; e < E_EXPERTS; ++e)
                acc[tk][e] += __shfl_xor_sync(0xffffffffu, acc[tk][e], off);

    if (lane == 0) {
#pragma unroll
        for (int tk = 0; tk < 4; ++tk) {
            float m = acc[tk][0]; int bi = 0;
#pragma unroll
            for (int e = 1; e < E_EXPERTS; ++e)
                if (acc[tk][e] > m) { m = acc[tk][e]; bi = e; }  // first-index ties
            float s = 0.f;
#pragma unroll
            for (int e = 0; e < E_EXPERTS; ++e)
                s += __expf(acc[tk][e] - m);
            g_gate[t0 + tk] = 1.0f / s;
            g_eidx[t0 + tk] = bi;
        }
    }
    __threadfence();                              // release results
    __syncthreads();
    if (threadIdx.x == 0) atomicAdd(&g_router_done, 1u);
}

// ---------------------------------------------------------------------------
// Scan: one 256-thread block, 32 rounds of 256 tokens. 1-based positions,
// capacity cutoff. Spins until all router blocks have published.
// ---------------------------------------------------------------------------
__device__ __forceinline__ void do_scan(int* s_cnt, int* s_off, int* s_base)
{
    const int tid  = threadIdx.x;
    const int warp = tid >> 5;
    const int lane = tid & 31;

    if (tid == 0) {
        while (*((volatile unsigned*)&g_router_done) < N_ROUTER_BLOCKS) __nanosleep(64);
        __threadfence();                          // acquire
    }
    __syncthreads();

    if (tid < E_EXPERTS) s_base[tid] = 0;
    __syncthreads();

    for (int r = 0; r < T_TOKENS / 256; ++r) {
        const int t = r * 256 + tid;
        const int e = __ldcg(&g_eidx[t]);
        int myrank = 0;
#pragma unroll
        for (int ex = 0; ex < E_EXPERTS; ++ex) {
            unsigned b = __ballot_sync(0xffffffffu, e == ex);
            if (e == ex) myrank = __popc(b & ((1u << lane) - 1u));
            if (lane == 0) s_cnt[warp * 8 + ex] = __popc(b);
        }
        __syncthreads();
        if (tid < E_EXPERTS) {                    // thread per expert scans 8 warps
            const int ex = tid;
            int run = s_base[ex];
#pragma unroll
            for (int w = 0; w < 8; ++w) {
                s_off[w * 8 + ex] = run;
                run += s_cnt[w * 8 + ex];
            }
            s_base[ex] = run;
        }
        __syncthreads();
        const int pos = s_off[warp * 8 + e] + myrank + 1;
        g_pos[t] = (pos < CAPACITY) ? pos : 0;
        __syncthreads();
    }
}

// ---------------------------------------------------------------------------
// Fill: pure zeros, no synchronization whatsoever. Token per block, 128 KiB.
// ---------------------------------------------------------------------------
__device__ __forceinline__ void do_fill(int t, float* __restrict__ out)
{
    const size_t TEC4 = (size_t)T_TOKENS * E_EXPERTS * (CAPACITY / 4);
    float4* d0 = (float4*)out + (size_t)t * E_EXPERTS * (CAPACITY / 4);
    float4* d1 = d0 + TEC4;
    const float4 z = make_float4(0.f, 0.f, 0.f, 0.f);
#pragma unroll
    for (int e = 0; e < E_EXPERTS; ++e)
#pragma unroll
        for (int k = 0; k < 2; ++k) {
            const int i = threadIdx.x + k * 256;  // 0..511 float4s
            d0[e * (CAPACITY / 4) + i] = z;
            d1[e * (CAPACITY / 4) + i] = z;
        }
}

// ---------------------------------------------------------------------------
// Fused kernel. Grid order == rough scheduling order:
//   bid 0..255   router (compact, finishes in first ~10us)
//   bid 256      scan (spins cheaply, one SM slot)
//   bid 257..    zero fill (8192 blocks, fence-free, DRAM-saturating)
// ---------------------------------------------------------------------------
__global__ __launch_bounds__(256) void fused_kernel(const float* __restrict__ x,
                                                    const float* __restrict__ W,
                                                    float* __restrict__ out)
{
    __shared__ float Wt[E_EXPERTS][D_DIM];        // 24 KB (router blocks)
    __shared__ int   s_cnt[8 * E_EXPERTS];
    __shared__ int   s_off[8 * E_EXPERTS];
    __shared__ int   s_base[E_EXPERTS];

    const int bid = blockIdx.x;
    if (bid < N_ROUTER_BLOCKS)      do_router(bid, x, W, Wt);
    else if (bid == SCAN_BID)       do_scan(s_cnt, s_off, s_base);
    else                            do_fill(bid - FILL_BASE, out);
}

// ---------------------------------------------------------------------------
// Scatter: normal launch after fused kernel -> stream ordering guarantees the
// zero fill and the scan are complete. 16K nonzero stores, ~2us.
// ---------------------------------------------------------------------------
__global__ __launch_bounds__(256) void scatter_kernel(float* __restrict__ out)
{
    const int t = blockIdx.x * blockDim.x + threadIdx.x;
    if (t >= T_TOKENS) return;
    const int pos = g_pos[t];
    if (pos == 0) return;
    const int e = g_eidx[t];
    const size_t TEC = (size_t)T_TOKENS * E_EXPERTS * CAPACITY;
    const size_t idx = ((size_t)t * E_EXPERTS + e) * CAPACITY + pos;
    out[idx]       = 1.0f;        // dispatch
    out[TEC + idx] = g_gate[t];   // combined
}

// ---------------------------------------------------------------------------
extern "C" void kernel_launch(void* const* d_in, const int* in_sizes, int n_in,
                              void* d_out, int out_size)
{
    const float* x = (const float*)d_in[0];
    const float* W = (const float*)d_in[1];
    float* out = (float*)d_out;

    init_kernel<<<1, 1>>>();
    fused_kernel<<<FILL_BASE + T_TOKENS, 256>>>(x, W, out);
    scatter_kernel<<<(T_TOKENS + 255) / 256, 256>>>(out);
}

// round 6
// speedup vs baseline: 1.3050x; 1.0273x over previous
#include <cuda_runtime.h>
#include <cuda_bf16.h>
#include <cstdint>

#define T_TOKENS 8192
#define D_DIM    768
#define E_EXPERTS 8
#define CAPACITY 2048

#define N_ROUTER_BLOCKS 256
#define SCAN_BID        N_ROUTER_BLOCKS
#define FILL_BASE       (N_ROUTER_BLOCKS + 1)

// Scratch (device globals — allocation is forbidden)
__device__ int      g_eidx[T_TOKENS];
__device__ float    g_gate[T_TOKENS];
__device__ int      g_pos[T_TOKENS];        // 1..2047 kept, 0 dropped
__device__ unsigned g_router_done = 0;      // reset by scatter_kernel each replay

// ---------------------------------------------------------------------------
// Router: warp handles 4 tokens, W float4 reused across them (LDS traffic /4).
// 256 blocks x 8 warps x 4 tokens = 8192.
// ---------------------------------------------------------------------------
__device__ __forceinline__ void do_router(int bid, const float* __restrict__ x,
                                          const float* __restrict__ W,
                                          float (*Wt)[D_DIM])
{
    for (int i = threadIdx.x; i < D_DIM * E_EXPERTS; i += 256) {
        int d = i >> 3, e = i & 7;
        Wt[e][d] = W[i];
    }
    __syncthreads();

    const int warp = threadIdx.x >> 5;
    const int lane = threadIdx.x & 31;
    const int t0 = (bid * 8 + warp) * 4;

    float acc[4][E_EXPERTS];
#pragma unroll
    for (int tk = 0; tk < 4; ++tk)
#pragma unroll
        for (int e = 0; e < E_EXPERTS; ++e) acc[tk][e] = 0.f;

#pragma unroll
    for (int i = 0; i < D_DIM / 128; ++i) {       // 6 iterations
        const int f4 = lane + 32 * i;
        float4 wv[E_EXPERTS];
#pragma unroll
        for (int e = 0; e < E_EXPERTS; ++e)
            wv[e] = *(const float4*)&Wt[e][4 * f4];
#pragma unroll
        for (int tk = 0; tk < 4; ++tk) {
            float4 xv = ((const float4*)(x + (size_t)(t0 + tk) * D_DIM))[f4];
#pragma unroll
            for (int e = 0; e < E_EXPERTS; ++e) {
                acc[tk][e] = fmaf(xv.x, wv[e].x, acc[tk][e]);
                acc[tk][e] = fmaf(xv.y, wv[e].y, acc[tk][e]);
                acc[tk][e] = fmaf(xv.z, wv[e].z, acc[tk][e]);
                acc[tk][e] = fmaf(xv.w, wv[e].w, acc[tk][e]);
            }
        }
    }
#pragma unroll
    for (int off = 16; off > 0; off >>= 1)
#pragma unroll
        for (int tk = 0; tk < 4; ++tk)
#pragma unroll
            for (int e = 0; e < E_EXPERTS; ++e)
                acc[tk][e] += __shfl_xor_sync(0xffffffffu, acc[tk][e], off);

    if (lane == 0) {
#pragma unroll
        for (int tk = 0; tk < 4; ++tk) {
            float m = acc[tk][0]; int bi = 0;
#pragma unroll
            for (int e = 1; e < E_EXPERTS; ++e)
                if (acc[tk][e] > m) { m = acc[tk][e]; bi = e; }  // first-index ties
            float s = 0.f;
#pragma unroll
            for (int e = 0; e < E_EXPERTS; ++e)
                s += __expf(acc[tk][e] - m);
            g_gate[t0 + tk] = 1.0f / s;
            g_eidx[t0 + tk] = bi;
        }
    }
    __threadfence();                              // release results
    __syncthreads();
    if (threadIdx.x == 0) atomicAdd(&g_router_done, 1u);
}

// ---------------------------------------------------------------------------
// Scan: one 256-thread block, 32 rounds of 256 tokens. 1-based positions,
// capacity cutoff. Spins until all router blocks have published.
// ---------------------------------------------------------------------------
__device__ __forceinline__ void do_scan(int* s_cnt, int* s_off, int* s_base)
{
    const int tid  = threadIdx.x;
    const int warp = tid >> 5;
    const int lane = tid & 31;

    if (tid == 0) {
        while (*((volatile unsigned*)&g_router_done) < N_ROUTER_BLOCKS) __nanosleep(64);
        __threadfence();                          // acquire
    }
    __syncthreads();

    if (tid < E_EXPERTS) s_base[tid] = 0;
    __syncthreads();

    for (int r = 0; r < T_TOKENS / 256; ++r) {
        const int t = r * 256 + tid;
        const int e = __ldcg(&g_eidx[t]);
        int myrank = 0;
#pragma unroll
        for (int ex = 0; ex < E_EXPERTS; ++ex) {
            unsigned b = __ballot_sync(0xffffffffu, e == ex);
            if (e == ex) myrank = __popc(b & ((1u << lane) - 1u));
            if (lane == 0) s_cnt[warp * 8 + ex] = __popc(b);
        }
        __syncthreads();
        if (tid < E_EXPERTS) {                    // thread per expert scans 8 warps
            const int ex = tid;
            int run = s_base[ex];
#pragma unroll
            for (int w = 0; w < 8; ++w) {
                s_off[w * 8 + ex] = run;
                run += s_cnt[w * 8 + ex];
            }
            s_base[ex] = run;
        }
        __syncthreads();
        const int pos = s_off[warp * 8 + e] + myrank + 1;
        g_pos[t] = (pos < CAPACITY) ? pos : 0;
        __syncthreads();
    }
}

// ---------------------------------------------------------------------------
// Fill: pure zeros, streaming stores, no synchronization. Token per block.
// ---------------------------------------------------------------------------
__device__ __forceinline__ void do_fill(int t, float* __restrict__ out)
{
    const size_t TEC4 = (size_t)T_TOKENS * E_EXPERTS * (CAPACITY / 4);
    float4* d0 = (float4*)out + (size_t)t * E_EXPERTS * (CAPACITY / 4);
    float4* d1 = d0 + TEC4;
    const float4 z = make_float4(0.f, 0.f, 0.f, 0.f);
#pragma unroll
    for (int e = 0; e < E_EXPERTS; ++e)
#pragma unroll
        for (int k = 0; k < 2; ++k) {
            const int i = threadIdx.x + k * 256;  // 0..511 float4s
            __stcs(&d0[e * (CAPACITY / 4) + i], z);
            __stcs(&d1[e * (CAPACITY / 4) + i], z);
        }
}

// ---------------------------------------------------------------------------
// Fused kernel. Grid order == rough scheduling order:
//   bid 0..255   router (compact, finishes in first ~10us)
//   bid 256      scan (spins cheaply, one SM slot)
//   bid 257..    zero fill (8192 blocks, fence-free, DRAM-saturating)
// ---------------------------------------------------------------------------
__global__ __launch_bounds__(256) void fused_kernel(const float* __restrict__ x,
                                                    const float* __restrict__ W,
                                                    float* __restrict__ out)
{
    __shared__ float Wt[E_EXPERTS][D_DIM];        // 24 KB (router blocks)
    __shared__ int   s_cnt[8 * E_EXPERTS];
    __shared__ int   s_off[8 * E_EXPERTS];
    __shared__ int   s_base[E_EXPERTS];

    const int bid = blockIdx.x;
    if (bid < N_ROUTER_BLOCKS)      do_router(bid, x, W, Wt);
    else if (bid == SCAN_BID)       do_scan(s_cnt, s_off, s_base);
    else                            do_fill(bid - FILL_BASE, out);
}

// ---------------------------------------------------------------------------
// Scatter: normal launch after fused kernel -> stream ordering guarantees the
// zero fill and the scan are complete. 16K nonzero stores, then resets the
// router counter for the next graph replay.
// ---------------------------------------------------------------------------
__global__ __launch_bounds__(256) void scatter_kernel(float* __restrict__ out)
{
    const int t = blockIdx.x * blockDim.x + threadIdx.x;
    if (blockIdx.x == 0 && threadIdx.x == 0)
        g_router_done = 0;                        // reset for next replay
    if (t >= T_TOKENS) return;
    const int pos = g_pos[t];
    if (pos == 0) return;
    const int e = g_eidx[t];
    const size_t TEC = (size_t)T_TOKENS * E_EXPERTS * CAPACITY;
    const size_t idx = ((size_t)t * E_EXPERTS + e) * CAPACITY + pos;
    out[idx]       = 1.0f;        // dispatch
    out[TEC + idx] = g_gate[t];   // combined
}

// ---------------------------------------------------------------------------
extern "C" void kernel_launch(void* const* d_in, const int* in_sizes, int n_in,
                              void* d_out, int out_size)
{
    const float* x = (const float*)d_in[0];
    const float* W = (const float*)d_in[1];
    float* out = (float*)d_out;

    fused_kernel<<<FILL_BASE + T_TOKENS, 256>>>(x, W, out);
    scatter_kernel<<<(T_TOKENS + 255) / 256, 256>>>(out);
}